// round 14
// baseline (speedup 1.0000x reference)
#include <cuda_runtime.h>
#include <cuda_fp16.h>
#include <stdint.h>

#define H      2048
#define FOURH  8192
#define TSEQ   2048
#define FUT    128
#define TOT    (TSEQ + FUT)
#define NB     148
#define NT     1024

#define GATE_STRIDE ((size_t)2048 * (size_t)H)

// pinned-weight blob slots (each slot = 1024 halfs = 4 gates x 256 k):
//   0..27  : m3 of layer-1 task w (w = warp 0..27)
//   28..59 : m3 of layer-2 taskA (warp 0..31)
//   60..83 : m3 of layer-2 taskB (warp 0..23 -> task warp+32)
//   84..103: m2 of layer-1 task w (w = 0..19)
#define PIN_TASKS 104
#define PIN_H     (PIN_TASKS * 1024)     // 106496 halfs per block
#define PIN_B     (PIN_H * 2)            // 212992 bytes

// dynamic smem layout
#define OFF_H    PIN_B                    // __half s_h[4096]  (8 KB)
#define OFF_G1   (OFF_H + 2 * H * 2)      // float s_g1[112]
#define OFF_G2   (OFF_G1 + 112 * 4)       // float s_g2[224]
#define SMEM_DYN (OFF_G2 + 224 * 4)       // 222,528 B

// ---------------- persistent device state ----------------
__device__ __align__(16) __half g_w1 [(size_t)FOURH * H];
__device__ __align__(16) __half g_w2i[(size_t)FOURH * H];
__device__ __align__(16) __half g_w2h[(size_t)FOURH * H];
__device__ __align__(16) __half g_pin[(size_t)NB * PIN_H];   // ~31.5 MB
__device__ float  g_b1[FOURH];
__device__ float  g_b2[FOURH];
__device__ __align__(16) __half g_h1[2][H];
__device__ __align__(16) __half g_h2[2][H];
__device__ float  g_part[2][NB];
__device__ unsigned g_count;
__device__ unsigned g_sense;

// ---------------- single merged prep kernel ----------------
__global__ void prep_all(const float* __restrict__ w_hh1,
                         const float* __restrict__ w_ih2,
                         const float* __restrict__ w_hh2,
                         const float* __restrict__ b_ih1,
                         const float* __restrict__ b_hh1,
                         const float* __restrict__ b_ih2,
                         const float* __restrict__ b_hh2)
{
    const size_t stride = (size_t)gridDim.x * blockDim.x;
    const size_t i0 = (size_t)blockIdx.x * blockDim.x + threadIdx.x;

    const size_t n = (size_t)FOURH * H;
    for (size_t k = i0; k < n; k += stride) {
        g_w1 [k] = __float2half_rn(w_hh1[k]);
        g_w2i[k] = __float2half_rn(w_ih2[k]);
        g_w2h[k] = __float2half_rn(w_hh2[k]);
    }

    const size_t ptotal = (size_t)NB * PIN_H;
    for (size_t idx = i0; idx < ptotal; idx += stride) {
        const int b  = (int)(idx / PIN_H);
        const int r  = (int)(idx % PIN_H);
        const int tk = r >> 10;
        const int g  = (r >> 8) & 3;
        const int kk = r & 255;
        const float* W; int j, k;
        if (tk < 28) {                       // m3 of layer-1 task tk
            j = b + (tk >> 1) * NB;
            k = (tk & 1) * 1024 + 768 + kk;
            W = w_hh1;
        } else if (tk < 60) {                // m3 of layer-2 taskA (warp tk-28)
            const int w = tk - 28;
            const int sub = w & 3;
            j = b + (w >> 2) * NB;
            k = (sub & 1) * 1024 + 768 + kk;
            W = (sub >> 1) ? w_hh2 : w_ih2;
        } else if (tk < 84) {                // m3 of layer-2 taskB (task (tk-60)+32)
            const int tb = (tk - 60) + 32;
            const int sub = tb & 3;
            j = b + (tb >> 2) * NB;
            k = (sub & 1) * 1024 + 768 + kk;
            W = (sub >> 1) ? w_hh2 : w_ih2;
        } else {                             // m2 of layer-1 task (tk-84), tasks 0..19
            const int w2 = tk - 84;
            j = b + (w2 >> 1) * NB;
            k = (w2 & 1) * 1024 + 512 + kk;
            W = w_hh1;
        }
        const float v = (j < H) ? W[(size_t)(g * H + j) * H + k] : 0.0f;
        g_pin[idx] = __float2half_rn(v);
    }

    if (i0 < FOURH) {
        g_b1[i0] = b_ih1[i0] + b_hh1[i0];
        g_b2[i0] = b_ih2[i0] + b_hh2[i0];
    }
    if (i0 < H) {
        g_h1[0][i0] = __float2half_rn(0.f); g_h1[1][i0] = __float2half_rn(0.f);
        g_h2[0][i0] = __float2half_rn(0.f); g_h2[1][i0] = __float2half_rn(0.f);
    }
    if (i0 < NB) { g_part[0][i0] = 0.f; g_part[1][i0] = 0.f; }
    if (i0 == 0) { g_count = 0u; g_sense = 0u; }
}

// ---------------- grid barrier: single atomic counter + monotonic sense (proven) ----
__device__ __forceinline__ void grid_sync(unsigned* phase)
{
    __syncthreads();
    if (threadIdx.x == 0) {
        const unsigned target = ++(*phase);
        __threadfence();
        if (atomicAdd(&g_count, 1u) == (unsigned)(NB - 1)) {
            g_count = 0u;
            __threadfence();
            atomicExch(&g_sense, target);
        } else {
            while (*((volatile unsigned*)&g_sense) < target) { }
            __threadfence();
        }
    }
    __syncthreads();
}

// HW tanh (MUFU.TANH)
__device__ __forceinline__ float tanhfast(float x)
{
    float y;
    asm("tanh.approx.f32 %0, %1;" : "=f"(y) : "f"(x));
    return y;
}
__device__ __forceinline__ float sigf(float x) { return 0.5f * tanhfast(0.5f * x) + 0.5f; }

// 8-term chunk: 4-deep HFMA2 chain in fp16, dumped once into fp32 accumulator
__device__ __forceinline__ void hdot8(const uint4& w, const uint4& h, float& a)
{
    const __half2* wp = reinterpret_cast<const __half2*>(&w);
    const __half2* hp = reinterpret_cast<const __half2*>(&h);
    __half2 s = __hmul2(wp[0], hp[0]);
    s = __hfma2(wp[1], hp[1], s);
    s = __hfma2(wp[2], hp[2], s);
    s = __hfma2(wp[3], hp[3], s);
    const float2 f = __half22float2(s);
    a += f.x + f.y;
}

// 4-gate dot: m0 from pre[], m1+m2 streamed (rotating), m3 pinned SMEM.
__device__ __forceinline__ void dot4h(const __half* __restrict__ w, const __half* hs,
                                      const __half* pin, int lane,
                                      float acc[4], uint4 pre[4])
{
    acc[0] = acc[1] = acc[2] = acc[3] = 0.0f;
    uint4 buf[4];
    #pragma unroll
    for (int m = 0; m < 3; ++m) {
        if (m < 2) {
            #pragma unroll
            for (int g = 0; g < 4; ++g)
                buf[g] = __ldg((const uint4*)(w + (size_t)g * GATE_STRIDE + (m + 1) * 256 + lane * 8));
        }
        const uint4 hv = *reinterpret_cast<const uint4*>(hs + m * 256 + lane * 8);
        #pragma unroll
        for (int g = 0; g < 4; ++g) hdot8(pre[g], hv, acc[g]);
        #pragma unroll
        for (int g = 0; g < 4; ++g) pre[g] = buf[g];
    }
    const uint4 hv3 = *reinterpret_cast<const uint4*>(hs + 768 + lane * 8);
    #pragma unroll
    for (int g = 0; g < 4; ++g) {
        const uint4 wv = *reinterpret_cast<const uint4*>(pin + g * 256 + lane * 8);
        hdot8(wv, hv3, acc[g]);
    }
}

// 4-gate dot with m2 AND m3 pinned: m0 from pre[], m1 streamed, m2/m3 SMEM.
__device__ __forceinline__ void dot4h_p2(const __half* __restrict__ w, const __half* hs,
                                         const __half* pin3, const __half* pin2, int lane,
                                         float acc[4], uint4 pre[4])
{
    uint4 b1[4];
    #pragma unroll
    for (int g = 0; g < 4; ++g)
        b1[g] = __ldg((const uint4*)(w + (size_t)g * GATE_STRIDE + 256 + lane * 8));

    acc[0] = acc[1] = acc[2] = acc[3] = 0.0f;
    const uint4 hv0 = *reinterpret_cast<const uint4*>(hs + lane * 8);
    #pragma unroll
    for (int g = 0; g < 4; ++g) hdot8(pre[g], hv0, acc[g]);
    const uint4 hv2 = *reinterpret_cast<const uint4*>(hs + 512 + lane * 8);
    #pragma unroll
    for (int g = 0; g < 4; ++g) {
        const uint4 wv = *reinterpret_cast<const uint4*>(pin2 + g * 256 + lane * 8);
        hdot8(wv, hv2, acc[g]);
    }
    const uint4 hv3 = *reinterpret_cast<const uint4*>(hs + 768 + lane * 8);
    #pragma unroll
    for (int g = 0; g < 4; ++g) {
        const uint4 wv = *reinterpret_cast<const uint4*>(pin3 + g * 256 + lane * 8);
        hdot8(wv, hv3, acc[g]);
    }
    const uint4 hv1 = *reinterpret_cast<const uint4*>(hs + 256 + lane * 8);
    #pragma unroll
    for (int g = 0; g < 4; ++g) hdot8(b1[g], hv1, acc[g]);
}

__device__ __forceinline__ void reduce4(float acc[4])
{
    #pragma unroll
    for (int g = 0; g < 4; ++g) {
        #pragma unroll
        for (int o = 16; o > 0; o >>= 1)
            acc[g] += __shfl_xor_sync(0xffffffffu, acc[g], o);
    }
}

// ---------------- main persistent kernel ----------------
__global__ void __launch_bounds__(NT, 1)
lstm_main(const float* __restrict__ input,
          const float* __restrict__ w_ih1,
          const float* __restrict__ w_lin,
          const float* __restrict__ b_lin,
          float* __restrict__ out)
{
    extern __shared__ __align__(16) char smem[];
    const __half* s_pin = (const __half*)smem;
    __half* s_h  = (__half*)(smem + OFF_H);   // [0:H) h1(t), [H:2H) h2(t-1), fp16
    float* s_g1  = (float*)(smem + OFF_G1);   // layer-1 dots for step t+1
    float* s_g2  = (float*)(smem + OFF_G2);   // layer-2 dots for step t

    const int b    = blockIdx.x;
    const int tid  = threadIdx.x;
    const int warp = tid >> 5;
    const int lane = tid & 31;
    const int nI   = (b < 124) ? 14 : 13;

    unsigned phase = 0;

    // layer-1 task (dot for step t+1): warp < 28 active
    const bool  t1  = (warp < 28) && ((warp >> 1) < nI);
    const bool  p2  = (warp < 20);
    const int   i1  = warp >> 1;
    const int   kh1 = warp & 1;
    const __half* w1p = g_w1 + (size_t)(b + i1 * NB) * H + kh1 * (H / 2);
    const __half* pin1 = s_pin + warp * 1024;
    const __half* pin1b = s_pin + (84 + warp) * 1024;

    // layer-2 tasks: tA = warp (always valid), tB = warp+32
    const int iA = warp >> 2, subA = warp & 3, srcA = subA >> 1, khA = subA & 1;
    const __half* wAp = (srcA ? g_w2h : g_w2i) + (size_t)(b + iA * NB) * H + khA * (H / 2);
    const __half* pinA = s_pin + (28 + warp) * 1024;
    const int tB = warp + 32;
    const bool tBv = (tB < nI * 4);
    const int iB = tB >> 2, subB = tB & 3, srcB = subB >> 1, khB = subB & 1;
    const __half* wBp = (srcB ? g_w2h : g_w2i) + (size_t)(b + iB * NB) * H + khB * (H / 2);
    const __half* pinB = s_pin + (60 + warp) * 1024;

    // one-time: pinned blob
    {
        const uint4* src = (const uint4*)(g_pin + (size_t)b * PIN_H);
        uint4* dst = (uint4*)smem;
        for (int i = tid; i < PIN_B / 16; i += NT) dst[i] = src[i];
    }
    for (int q = tid; q < 2 * H; q += NT) s_h[q] = __float2half_rn(0.f);

    const float blin = __ldg(b_lin);
    float c1v = 0.0f;   // warp-1 lane-resident
    float c2v = 0.0f;   // warp-0 lane-resident

    // ---- preamble: ew1(0) on warp 1 (h=0, c=0 -> dots are zero) ----
    if (warp == 1 && lane < nI) {
        const float x = __ldg(input);       // input[0]
        const int j = b + lane * NB;
        const float gi = g_b1[j]        + __ldg(w_ih1 + j)        * x;
        const float gf = g_b1[j + 2048] + __ldg(w_ih1 + j + 2048) * x;
        const float gg = g_b1[j + 4096] + __ldg(w_ih1 + j + 4096) * x;
        const float go = g_b1[j + 6144] + __ldg(w_ih1 + j + 6144) * x;
        c1v = sigf(gf) * c1v + sigf(gi) * tanhfast(gg);
        g_h1[0][j] = __float2half_rn(sigf(go) * tanhfast(c1v));
    }

    // prime layer-2 taskA m=0 for t=0 (crosses the initial barrier)
    uint4 preA[4];
    #pragma unroll
    for (int g = 0; g < 4; ++g)
        preA[g] = __ldg((const uint4*)(wAp + (size_t)g * GATE_STRIDE + lane * 8));

    float xnext = 0.0f; // warp-1 resident recurrent scalar (closed loop)

    for (int t = 0; t < TOT; ++t) {
        const int cur  = t & 1;
        const int prev = cur ^ 1;

        grid_sync(&phase);            // ===== barrier A: publishes h1(t), g_part[t-1] =====

        // ---- lazy output for step t-1 (open-loop only; block 0) ----
        if (b == 0 && warp == 0 && t > 0 && (t - 1) < TSEQ - 1) {
            float s = 0.0f;
            #pragma unroll
            for (int p = lane; p < NB; p += 32) s += __ldcg(&g_part[prev][p]);
            #pragma unroll
            for (int o = 16; o > 0; o >>= 1) s += __shfl_xor_sync(0xffffffffu, s, o);
            if (lane == 0) out[t - 1] = s + blin;
        }

        // ---- stage h1(t) | h2(t-1) : 512 x uint4 ----
        if (tid < 512) {
            uint4 v;
            if (tid < 256)
                v = __ldcg(((const uint4*)&g_h1[cur][0]) + tid);
            else
                v = __ldcg(((const uint4*)&g_h2[prev][0]) + (tid - 256));
            ((uint4*)s_h)[tid] = v;
        }
        __syncthreads();

        // ================= fused dots: dotA(t), dotB(t), dot1(t+1) =================
        uint4 preB[4];
        if (tBv) {
            #pragma unroll
            for (int g = 0; g < 4; ++g)
                preB[g] = __ldg((const uint4*)(wBp + (size_t)g * GATE_STRIDE + lane * 8));
        }
        {
            float acc[4];
            dot4h(wAp, s_h + srcA * H + khA * (H / 2), pinA, lane, acc, preA);
            reduce4(acc);
            if (lane == 0) {
                #pragma unroll
                for (int g = 0; g < 4; ++g) s_g2[iA * 16 + g * 4 + subA] = acc[g];
            }
        }
        uint4 pre1[4];
        if (t1) {
            #pragma unroll
            for (int g = 0; g < 4; ++g)
                pre1[g] = __ldg((const uint4*)(w1p + (size_t)g * GATE_STRIDE + lane * 8));
        }
        if (tBv) {
            float acc[4];
            dot4h(wBp, s_h + srcB * H + khB * (H / 2), pinB, lane, acc, preB);
            reduce4(acc);
            if (lane == 0) {
                #pragma unroll
                for (int g = 0; g < 4; ++g) s_g2[iB * 16 + g * 4 + subB] = acc[g];
            }
        }
        if (t1) {   // layer-1 dot for step t+1, reads s_h[0:H) = h1(t)
            float acc[4];
            if (p2) dot4h_p2(w1p, s_h + kh1 * (H / 2), pin1, pin1b, lane, acc, pre1);
            else    dot4h   (w1p, s_h + kh1 * (H / 2), pin1, lane, acc, pre1);
            reduce4(acc);
            if (lane == 0) {
                #pragma unroll
                for (int g = 0; g < 4; ++g) s_g1[i1 * 8 + g * 2 + kh1] = acc[g];
            }
        }
        __syncthreads();

        // ================= elementwise: ew2(t) on warp 0  ||  ew1(t+1) on warp 1 =====
        if (warp == 0) {
            float contrib = 0.0f;
            if (lane < nI) {
                const int j = b + lane * NB;
                const float gi = s_g2[lane*16+ 0] + s_g2[lane*16+ 1] + s_g2[lane*16+ 2] + s_g2[lane*16+ 3] + g_b2[j];
                const float gf = s_g2[lane*16+ 4] + s_g2[lane*16+ 5] + s_g2[lane*16+ 6] + s_g2[lane*16+ 7] + g_b2[j + 2048];
                const float gg = s_g2[lane*16+ 8] + s_g2[lane*16+ 9] + s_g2[lane*16+10] + s_g2[lane*16+11] + g_b2[j + 4096];
                const float go = s_g2[lane*16+12] + s_g2[lane*16+13] + s_g2[lane*16+14] + s_g2[lane*16+15] + g_b2[j + 6144];
                c2v = sigf(gf) * c2v + sigf(gi) * tanhfast(gg);
                const float h = sigf(go) * tanhfast(c2v);
                g_h2[cur][j] = __float2half_rn(h);
                contrib = h * __ldg(w_lin + j);
            }
            #pragma unroll
            for (int o = 16; o > 0; o >>= 1) contrib += __shfl_xor_sync(0xffffffffu, contrib, o);
            if (lane == 0) g_part[cur][b] = contrib;
        }
        if (warp == 1 && (t + 1) < TSEQ && lane < nI) {
            // open-loop ew1(t+1): x comes straight from input
            const float x = __ldg(input + t + 1);
            const int j = b + lane * NB;
            const float gi = s_g1[lane*8+0] + s_g1[lane*8+1] + g_b1[j]        + __ldg(w_ih1 + j)        * x;
            const float gf = s_g1[lane*8+2] + s_g1[lane*8+3] + g_b1[j + 2048] + __ldg(w_ih1 + j + 2048) * x;
            const float gg = s_g1[lane*8+4] + s_g1[lane*8+5] + g_b1[j + 4096] + __ldg(w_ih1 + j + 4096) * x;
            const float go = s_g1[lane*8+6] + s_g1[lane*8+7] + g_b1[j + 6144] + __ldg(w_ih1 + j + 6144) * x;
            c1v = sigf(gf) * c1v + sigf(gi) * tanhfast(gg);
            g_h1[prev][j] = __float2half_rn(sigf(go) * tanhfast(c1v));   // prev == (t+1)&1
        }

        // prefetch next iteration's taskA m=0 (crosses barrier A of t+1)
        #pragma unroll
        for (int g = 0; g < 4; ++g)
            preA[g] = __ldg((const uint4*)(wAp + (size_t)g * GATE_STRIDE + lane * 8));

        // ===== closed loop: barrier B, scalar feedback, ew1(t+1) with x = out(t) =====
        if (t >= TSEQ - 1) {
            grid_sync(&phase);
            if (warp <= 1) {
                float s = 0.0f;
                #pragma unroll
                for (int p = lane; p < NB; p += 32) s += __ldcg(&g_part[cur][p]);
                #pragma unroll
                for (int o = 16; o > 0; o >>= 1) s += __shfl_xor_sync(0xffffffffu, s, o);
                xnext = s + blin;
                if (warp == 0 && b == 0 && lane == 0) out[t] = xnext;
                if (warp == 1 && (t + 1) < TOT && lane < nI) {
                    const float x = xnext;
                    const int j = b + lane * NB;
                    const float gi = s_g1[lane*8+0] + s_g1[lane*8+1] + g_b1[j]        + __ldg(w_ih1 + j)        * x;
                    const float gf = s_g1[lane*8+2] + s_g1[lane*8+3] + g_b1[j + 2048] + __ldg(w_ih1 + j + 2048) * x;
                    const float gg = s_g1[lane*8+4] + s_g1[lane*8+5] + g_b1[j + 4096] + __ldg(w_ih1 + j + 4096) * x;
                    const float go = s_g1[lane*8+6] + s_g1[lane*8+7] + g_b1[j + 6144] + __ldg(w_ih1 + j + 6144) * x;
                    c1v = sigf(gf) * c1v + sigf(gi) * tanhfast(gg);
                    g_h1[prev][j] = __float2half_rn(sigf(go) * tanhfast(c1v));
                }
            }
        }
    }
}

// ---------------- launch ----------------
extern "C" void kernel_launch(void* const* d_in, const int* in_sizes, int n_in,
                              void* d_out, int out_size)
{
    const float* input = (const float*)d_in[0];
    const float* w_ih1 = (const float*)d_in[1];
    const float* w_hh1 = (const float*)d_in[2];
    const float* b_ih1 = (const float*)d_in[3];
    const float* b_hh1 = (const float*)d_in[4];
    const float* w_ih2 = (const float*)d_in[5];
    const float* w_hh2 = (const float*)d_in[6];
    const float* b_ih2 = (const float*)d_in[7];
    const float* b_hh2 = (const float*)d_in[8];
    const float* w_lin = (const float*)d_in[9];
    const float* b_lin = (const float*)d_in[10];
    float* out = (float*)d_out;

    static int smem_set = 0;
    if (!smem_set) {
        cudaFuncSetAttribute(lstm_main, cudaFuncAttributeMaxDynamicSharedMemorySize, SMEM_DYN);
        smem_set = 1;
    }

    prep_all<<<2048, 256>>>(w_hh1, w_ih2, w_hh2, b_ih1, b_hh1, b_ih2, b_hh2);
    lstm_main<<<NB, NT, SMEM_DYN>>>(input, w_ih1, w_lin, b_lin, out);
}

// round 15
// speedup vs baseline: 1.2300x; 1.2300x over previous
#include <cuda_runtime.h>
#include <cuda_fp16.h>
#include <stdint.h>

#define H      2048
#define FOURH  8192
#define TSEQ   2048
#define FUT    128
#define TOT    (TSEQ + FUT)
#define NB     148
#define NT     1024

#define GATE_STRIDE ((size_t)2048 * (size_t)H)

// pinned-weight blob slots (each slot = 1024 halfs = 4 gates x 256 k):
//   0..27  : m3 of layer-1 task w (w = warp 0..27)
//   28..59 : m3 of layer-2 taskA (warp 0..31)
//   60..83 : m3 of layer-2 taskB (warp 0..23 -> task warp+32)
//   84..103: m2 of layer-1 task w (w = 0..19)
#define PIN_TASKS 104
#define PIN_H     (PIN_TASKS * 1024)     // 106496 halfs per block
#define PIN_B     (PIN_H * 2)            // 212992 bytes

// dynamic smem layout
#define OFF_H    PIN_B                    // __half s_h[4096]  (8 KB)
#define OFF_G1   (OFF_H + 2 * H * 2)      // float s_g1[112]
#define OFF_G2   (OFF_G1 + 112 * 4)       // float s_g2[224]
#define SMEM_DYN (OFF_G2 + 224 * 4)       // 222,528 B

// ---------------- persistent device state ----------------
__device__ __align__(16) __half g_w1 [(size_t)FOURH * H];
__device__ __align__(16) __half g_w2i[(size_t)FOURH * H];
__device__ __align__(16) __half g_w2h[(size_t)FOURH * H];
__device__ __align__(16) __half g_pin[(size_t)NB * PIN_H];   // ~31.5 MB
__device__ float  g_b1[FOURH];
__device__ float  g_b2[FOURH];
__device__ __align__(16) __half g_h1[2][H];
__device__ __align__(16) __half g_h2[2][H];
__device__ float  g_partall[TOT][NB];       // per-step per-block output partials (~1.3 MB)
__device__ unsigned g_count;
__device__ unsigned g_sense;

// ---------------- single merged prep kernel ----------------
__global__ void prep_all(const float* __restrict__ w_hh1,
                         const float* __restrict__ w_ih2,
                         const float* __restrict__ w_hh2,
                         const float* __restrict__ b_ih1,
                         const float* __restrict__ b_hh1,
                         const float* __restrict__ b_ih2,
                         const float* __restrict__ b_hh2)
{
    const size_t stride = (size_t)gridDim.x * blockDim.x;
    const size_t i0 = (size_t)blockIdx.x * blockDim.x + threadIdx.x;

    const size_t n = (size_t)FOURH * H;
    for (size_t k = i0; k < n; k += stride) {
        g_w1 [k] = __float2half_rn(w_hh1[k]);
        g_w2i[k] = __float2half_rn(w_ih2[k]);
        g_w2h[k] = __float2half_rn(w_hh2[k]);
    }

    const size_t ptotal = (size_t)NB * PIN_H;
    for (size_t idx = i0; idx < ptotal; idx += stride) {
        const int b  = (int)(idx / PIN_H);
        const int r  = (int)(idx % PIN_H);
        const int tk = r >> 10;
        const int g  = (r >> 8) & 3;
        const int kk = r & 255;
        const float* W; int j, k;
        if (tk < 28) {                       // m3 of layer-1 task tk
            j = b + (tk >> 1) * NB;
            k = (tk & 1) * 1024 + 768 + kk;
            W = w_hh1;
        } else if (tk < 60) {                // m3 of layer-2 taskA (warp tk-28)
            const int w = tk - 28;
            const int sub = w & 3;
            j = b + (w >> 2) * NB;
            k = (sub & 1) * 1024 + 768 + kk;
            W = (sub >> 1) ? w_hh2 : w_ih2;
        } else if (tk < 84) {                // m3 of layer-2 taskB (task (tk-60)+32)
            const int tb = (tk - 60) + 32;
            const int sub = tb & 3;
            j = b + (tb >> 2) * NB;
            k = (sub & 1) * 1024 + 768 + kk;
            W = (sub >> 1) ? w_hh2 : w_ih2;
        } else {                             // m2 of layer-1 task (tk-84), tasks 0..19
            const int w2 = tk - 84;
            j = b + (w2 >> 1) * NB;
            k = (w2 & 1) * 1024 + 512 + kk;
            W = w_hh1;
        }
        const float v = (j < H) ? W[(size_t)(g * H + j) * H + k] : 0.0f;
        g_pin[idx] = __float2half_rn(v);
    }

    if (i0 < FOURH) {
        g_b1[i0] = b_ih1[i0] + b_hh1[i0];
        g_b2[i0] = b_ih2[i0] + b_hh2[i0];
    }
    if (i0 < H) {
        g_h1[0][i0] = __float2half_rn(0.f); g_h1[1][i0] = __float2half_rn(0.f);
        g_h2[0][i0] = __float2half_rn(0.f); g_h2[1][i0] = __float2half_rn(0.f);
    }
    if (i0 == 0) { g_count = 0u; g_sense = 0u; }
}

// ---------------- grid barrier: single atomic counter + monotonic sense (proven) ----
__device__ __forceinline__ void grid_sync(unsigned* phase)
{
    __syncthreads();
    if (threadIdx.x == 0) {
        const unsigned target = ++(*phase);
        __threadfence();
        if (atomicAdd(&g_count, 1u) == (unsigned)(NB - 1)) {
            g_count = 0u;
            __threadfence();
            atomicExch(&g_sense, target);
        } else {
            while (*((volatile unsigned*)&g_sense) < target) { }
            __threadfence();
        }
    }
    __syncthreads();
}

// HW tanh (MUFU.TANH, ~1-2e-4 abs err — below fp16-h quantization)
__device__ __forceinline__ float tanhfast(float x)
{
    float y;
    asm("tanh.approx.f32 %0, %1;" : "=f"(y) : "f"(x));
    return y;
}
__device__ __forceinline__ float sigf(float x) { return 0.5f * tanhfast(0.5f * x) + 0.5f; }

// 8-term chunk: 4-deep HFMA2 chain in fp16, dumped once into fp32 accumulator
__device__ __forceinline__ void hdot8(const uint4& w, const uint4& h, float& a)
{
    const __half2* wp = reinterpret_cast<const __half2*>(&w);
    const __half2* hp = reinterpret_cast<const __half2*>(&h);
    __half2 s = __hmul2(wp[0], hp[0]);
    s = __hfma2(wp[1], hp[1], s);
    s = __hfma2(wp[2], hp[2], s);
    s = __hfma2(wp[3], hp[3], s);
    const float2 f = __half22float2(s);
    a += f.x + f.y;
}

// 4-gate dot: m0 from pre[], m1+m2 streamed (rotating), m3 pinned SMEM.
__device__ __forceinline__ void dot4h(const __half* __restrict__ w, const __half* hs,
                                      const __half* pin, int lane,
                                      float acc[4], uint4 pre[4])
{
    acc[0] = acc[1] = acc[2] = acc[3] = 0.0f;
    uint4 buf[4];
    #pragma unroll
    for (int m = 0; m < 3; ++m) {
        if (m < 2) {
            #pragma unroll
            for (int g = 0; g < 4; ++g)
                buf[g] = __ldg((const uint4*)(w + (size_t)g * GATE_STRIDE + (m + 1) * 256 + lane * 8));
        }
        const uint4 hv = *reinterpret_cast<const uint4*>(hs + m * 256 + lane * 8);
        #pragma unroll
        for (int g = 0; g < 4; ++g) hdot8(pre[g], hv, acc[g]);
        #pragma unroll
        for (int g = 0; g < 4; ++g) pre[g] = buf[g];
    }
    const uint4 hv3 = *reinterpret_cast<const uint4*>(hs + 768 + lane * 8);
    #pragma unroll
    for (int g = 0; g < 4; ++g) {
        const uint4 wv = *reinterpret_cast<const uint4*>(pin + g * 256 + lane * 8);
        hdot8(wv, hv3, acc[g]);
    }
}

// 4-gate dot with m2 AND m3 pinned: m0 from pre[], m1 streamed, m2/m3 SMEM.
// Order: m0, m2, m3, m1 (m1 arrives while SMEM groups compute).
__device__ __forceinline__ void dot4h_p2(const __half* __restrict__ w, const __half* hs,
                                         const __half* pin3, const __half* pin2, int lane,
                                         float acc[4], uint4 pre[4])
{
    uint4 b1[4];
    #pragma unroll
    for (int g = 0; g < 4; ++g)
        b1[g] = __ldg((const uint4*)(w + (size_t)g * GATE_STRIDE + 256 + lane * 8));

    acc[0] = acc[1] = acc[2] = acc[3] = 0.0f;
    const uint4 hv0 = *reinterpret_cast<const uint4*>(hs + lane * 8);
    #pragma unroll
    for (int g = 0; g < 4; ++g) hdot8(pre[g], hv0, acc[g]);
    const uint4 hv2 = *reinterpret_cast<const uint4*>(hs + 512 + lane * 8);
    #pragma unroll
    for (int g = 0; g < 4; ++g) {
        const uint4 wv = *reinterpret_cast<const uint4*>(pin2 + g * 256 + lane * 8);
        hdot8(wv, hv2, acc[g]);
    }
    const uint4 hv3 = *reinterpret_cast<const uint4*>(hs + 768 + lane * 8);
    #pragma unroll
    for (int g = 0; g < 4; ++g) {
        const uint4 wv = *reinterpret_cast<const uint4*>(pin3 + g * 256 + lane * 8);
        hdot8(wv, hv3, acc[g]);
    }
    const uint4 hv1 = *reinterpret_cast<const uint4*>(hs + 256 + lane * 8);
    #pragma unroll
    for (int g = 0; g < 4; ++g) hdot8(b1[g], hv1, acc[g]);
}

__device__ __forceinline__ void reduce4(float acc[4])
{
    #pragma unroll
    for (int g = 0; g < 4; ++g) {
        #pragma unroll
        for (int o = 16; o > 0; o >>= 1)
            acc[g] += __shfl_xor_sync(0xffffffffu, acc[g], o);
    }
}

// ---------------- main persistent kernel ----------------
__global__ void __launch_bounds__(NT, 1)
lstm_main(const float* __restrict__ input,
          const float* __restrict__ w_ih1,
          const float* __restrict__ w_lin,
          const float* __restrict__ b_lin,
          float* __restrict__ out)
{
    extern __shared__ __align__(16) char smem[];
    const __half* s_pin = (const __half*)smem;
    __half* s_h  = (__half*)(smem + OFF_H);   // [0:H) h1, [H:2H) h2(prev), fp16
    float* s_g1  = (float*)(smem + OFF_G1);   // [i*8 + g*2 + kh]
    float* s_g2  = (float*)(smem + OFF_G2);   // [i*16 + g*4 + sub]

    const int b    = blockIdx.x;
    const int tid  = threadIdx.x;
    const int warp = tid >> 5;
    const int lane = tid & 31;
    const int nI   = (b < 124) ? 14 : 13;

    unsigned phase = 0;

    // layer-1 task: warp < 28 active
    const bool  t1  = (warp < 28) && ((warp >> 1) < nI);
    const bool  p2  = (warp < 20);            // layer-1 tasks with m2 pinned
    const int   i1  = warp >> 1;
    const int   kh1 = warp & 1;
    const __half* w1p = g_w1 + (size_t)(b + i1 * NB) * H + kh1 * (H / 2);
    const __half* pin1 = s_pin + warp * 1024;
    const __half* pin1b = s_pin + (84 + warp) * 1024;

    // layer-2 tasks: tA = warp (always valid), tB = warp+32
    const int iA = warp >> 2, subA = warp & 3, srcA = subA >> 1, khA = subA & 1;
    const __half* wAp = (srcA ? g_w2h : g_w2i) + (size_t)(b + iA * NB) * H + khA * (H / 2);
    const __half* pinA = s_pin + (28 + warp) * 1024;
    const int tB = warp + 32;
    const bool tBv = (tB < nI * 4);
    const int iB = tB >> 2, subB = tB & 3, srcB = subB >> 1, khB = subB & 1;
    const __half* wBp = (srcB ? g_w2h : g_w2i) + (size_t)(b + iB * NB) * H + khB * (H / 2);
    const __half* pinB = s_pin + (60 + warp) * 1024;

    // one-time: pinned blob, zero s_h
    {
        const uint4* src = (const uint4*)(g_pin + (size_t)b * PIN_H);
        uint4* dst = (uint4*)smem;
        for (int i = tid; i < PIN_B / 16; i += NT) dst[i] = src[i];
    }
    for (int q = tid; q < 2 * H; q += NT) s_h[q] = __float2half_rn(0.f);
    __syncthreads();

    const float blin = __ldg(b_lin);
    float c1v = 0.0f, c2v = 0.0f;
    float xnext = 0.0f;

    // prime layer-1 m=0 for t=0
    uint4 pre1[4];
    if (t1) {
        #pragma unroll
        for (int g = 0; g < 4; ++g)
            pre1[g] = __ldg((const uint4*)(w1p + (size_t)g * GATE_STRIDE + lane * 8));
    }

    for (int t = 0; t < TOT; ++t) {
        const int cur  = t & 1;
        const int prev = cur ^ 1;

        // ================= layer 1 (reads s_h[0:H) = h1(t-1)) =================
        if (t1) {
            float acc[4];
            if (p2) dot4h_p2(w1p, s_h + kh1 * (H / 2), pin1, pin1b, lane, acc, pre1);
            else    dot4h   (w1p, s_h + kh1 * (H / 2), pin1, lane, acc, pre1);
            reduce4(acc);
            if (lane == 0) {
                #pragma unroll
                for (int g = 0; g < 4; ++g) s_g1[i1 * 8 + g * 2 + kh1] = acc[g];
            }
        }
        __syncthreads();

        // ---- layer-1 elementwise (warp 0) ----
        if (warp == 0 && lane < nI) {
            const float x = (t < TSEQ) ? __ldg(input + t) : xnext;
            const int j = b + lane * NB;
            const float gi = s_g1[lane*8+0] + s_g1[lane*8+1] + g_b1[j]        + __ldg(w_ih1 + j)        * x;
            const float gf = s_g1[lane*8+2] + s_g1[lane*8+3] + g_b1[j + 2048] + __ldg(w_ih1 + j + 2048) * x;
            const float gg = s_g1[lane*8+4] + s_g1[lane*8+5] + g_b1[j + 4096] + __ldg(w_ih1 + j + 4096) * x;
            const float go = s_g1[lane*8+6] + s_g1[lane*8+7] + g_b1[j + 6144] + __ldg(w_ih1 + j + 6144) * x;
            c1v = sigf(gf) * c1v + sigf(gi) * tanhfast(gg);
            g_h1[cur][j] = __float2half_rn(sigf(go) * tanhfast(c1v));
        }

        // prefetch layer-2 task A m=0 (crosses barrier A)
        uint4 preA[4];
        #pragma unroll
        for (int g = 0; g < 4; ++g)
            preA[g] = __ldg((const uint4*)(wAp + (size_t)g * GATE_STRIDE + lane * 8));

        grid_sync(&phase);            // ===== barrier A =====

        // ---- stage h1(cur) | h2(prev) : 512 x uint4 (8 halfs each) ----
        if (tid < 512) {
            uint4 v;
            if (tid < 256)
                v = __ldcg(((const uint4*)&g_h1[cur][0]) + tid);
            else
                v = __ldcg(((const uint4*)&g_h2[prev][0]) + (tid - 256));
            ((uint4*)s_h)[tid] = v;
        }
        __syncthreads();

        // ================= layer 2: task A, then task B =================
        {
            float acc[4];
            dot4h(wAp, s_h + srcA * H + khA * (H / 2), pinA, lane, acc, preA);
            reduce4(acc);
            if (lane == 0) {
                #pragma unroll
                for (int g = 0; g < 4; ++g) s_g2[iA * 16 + g * 4 + subA] = acc[g];
            }
        }
        if (tBv) {
            uint4 preB[4];
            #pragma unroll
            for (int g = 0; g < 4; ++g)
                preB[g] = __ldg((const uint4*)(wBp + (size_t)g * GATE_STRIDE + lane * 8));
            float acc[4];
            dot4h(wBp, s_h + srcB * H + khB * (H / 2), pinB, lane, acc, preB);
            reduce4(acc);
            if (lane == 0) {
                #pragma unroll
                for (int g = 0; g < 4; ++g) s_g2[iB * 16 + g * 4 + subB] = acc[g];
            }
        }
        __syncthreads();

        // prefetch next step's layer-1 m=0 (covers ew2 + loop tail)
        if (t1) {
            #pragma unroll
            for (int g = 0; g < 4; ++g)
                pre1[g] = __ldg((const uint4*)(w1p + (size_t)g * GATE_STRIDE + lane * 8));
        }

        // ---- layer-2 elementwise + block partial (warp 0, shuffle-reduced) ----
        if (warp == 0) {
            float contrib = 0.0f;
            if (lane < nI) {
                const int j = b + lane * NB;
                const float gi = s_g2[lane*16+ 0] + s_g2[lane*16+ 1] + s_g2[lane*16+ 2] + s_g2[lane*16+ 3] + g_b2[j];
                const float gf = s_g2[lane*16+ 4] + s_g2[lane*16+ 5] + s_g2[lane*16+ 6] + s_g2[lane*16+ 7] + g_b2[j + 2048];
                const float gg = s_g2[lane*16+ 8] + s_g2[lane*16+ 9] + s_g2[lane*16+10] + s_g2[lane*16+11] + g_b2[j + 4096];
                const float go = s_g2[lane*16+12] + s_g2[lane*16+13] + s_g2[lane*16+14] + s_g2[lane*16+15] + g_b2[j + 6144];
                c2v = sigf(gf) * c2v + sigf(gi) * tanhfast(gg);
                const float h = sigf(go) * tanhfast(c2v);
                g_h2[cur][j] = __float2half_rn(h);
                contrib = h * __ldg(w_lin + j);
            }
            #pragma unroll
            for (int o = 16; o > 0; o >>= 1) contrib += __shfl_xor_sync(0xffffffffu, contrib, o);
            if (lane == 0) g_partall[t][b] = contrib;    // logged; reduced lazily
        }

        // ===== barrier B only when the scalar output feeds back (or final step) =====
        if (t >= TSEQ - 1) {
            grid_sync(&phase);
            if (warp == 0) {
                float s = 0.0f;
                #pragma unroll
                for (int p = lane; p < NB; p += 32) s += __ldcg(&g_partall[t][p]);
                #pragma unroll
                for (int o = 16; o > 0; o >>= 1) s += __shfl_xor_sync(0xffffffffu, s, o);
                xnext = s + blin;
                if (b == 0 && lane == 0) out[t] = xnext;
            }
        }
    }

    // ================= epilogue: reduce all open-loop outputs in parallel =========
    grid_sync(&phase);
    {
        const int task = b * 32 + warp;       // 4736 warps >= 2047 tasks
        if (task < TSEQ - 1) {
            float s = 0.0f;
            #pragma unroll
            for (int p = lane; p < NB; p += 32) s += __ldcg(&g_partall[task][p]);
            #pragma unroll
            for (int o = 16; o > 0; o >>= 1) s += __shfl_xor_sync(0xffffffffu, s, o);
            if (lane == 0) out[task] = s + blin;
        }
    }
}

// ---------------- launch ----------------
extern "C" void kernel_launch(void* const* d_in, const int* in_sizes, int n_in,
                              void* d_out, int out_size)
{
    const float* input = (const float*)d_in[0];
    const float* w_ih1 = (const float*)d_in[1];
    const float* w_hh1 = (const float*)d_in[2];
    const float* b_ih1 = (const float*)d_in[3];
    const float* b_hh1 = (const float*)d_in[4];
    const float* w_ih2 = (const float*)d_in[5];
    const float* w_hh2 = (const float*)d_in[6];
    const float* b_ih2 = (const float*)d_in[7];
    const float* b_hh2 = (const float*)d_in[8];
    const float* w_lin = (const float*)d_in[9];
    const float* b_lin = (const float*)d_in[10];
    float* out = (float*)d_out;

    static int smem_set = 0;
    if (!smem_set) {
        cudaFuncSetAttribute(lstm_main, cudaFuncAttributeMaxDynamicSharedMemorySize, SMEM_DYN);
        smem_set = 1;
    }

    prep_all<<<2048, 256>>>(w_hh1, w_ih2, w_hh2, b_ih1, b_hh1, b_ih2, b_hh2);
    lstm_main<<<NB, NT, SMEM_DYN>>>(input, w_ih1, w_lin, b_lin, out);
}